// round 7
// baseline (speedup 1.0000x reference)
#include <cuda_runtime.h>

#define N_NODES 50000
#define N_EDGES 1600000
#define N_LABEL 200000
#define IN_C    128
#define HID1    256
#define HID2    32

#define SCAN_BLK 1024
#define N_SCAN_BLOCKS ((N_NODES + SCAN_BLK - 1) / SCAN_BLK)   // 49

// fused kernel smem layout (words)
#define AS_WORDS 16896                 // max(128*132 S1-tile, 256*36 W2s)
#define BS_WORDS 33792                 // max(128*264 W1s, 128*260 Hs)
#define SMEM_WORDS (AS_WORDS + BS_WORDS)          // 50688 words = 202752 B

// ---------------- device scratch ----------------
__device__ __align__(256) int   g_cnt   [N_NODES];
__device__ __align__(256) int   g_rowptr[N_NODES + 1];
__device__ __align__(256) int   g_cursor[N_NODES];
__device__ __align__(256) int   g_csrc  [N_EDGES];
__device__ __align__(256) int   g_bsum  [64];
__device__ __align__(256) int   g_boff  [64];
__device__ __align__(256) float g_dinv  [N_NODES];
__device__ __align__(256) float g_ts    [N_NODES * HID2];
__device__ __align__(256) float g_z     [N_NODES * HID2];

// ---------------- tf32 helpers ----------------
__device__ __forceinline__ unsigned f2tf32(float f) {
    unsigned r;
    asm("cvt.rna.tf32.f32 %0, %1;" : "=r"(r) : "f"(f));
    return r;
}
__device__ __forceinline__ void mma_tf32(float* c, unsigned a0, unsigned a1,
                                         unsigned a2, unsigned a3,
                                         unsigned b0, unsigned b1) {
    asm volatile(
        "mma.sync.aligned.m16n8k8.row.col.f32.tf32.tf32.f32 "
        "{%0,%1,%2,%3}, {%4,%5,%6,%7}, {%8,%9}, {%0,%1,%2,%3};"
        : "+f"(c[0]), "+f"(c[1]), "+f"(c[2]), "+f"(c[3])
        : "r"(a0), "r"(a1), "r"(a2), "r"(a3), "r"(b0), "r"(b1));
}

// ---------------- CSR build ----------------
__global__ void k_zero_cnt() {
    int i = blockIdx.x * blockDim.x + threadIdx.x;
    if (i < N_NODES) g_cnt[i] = 0;
}

__global__ void k_hist(const int* __restrict__ ei) {
    int e = blockIdx.x * blockDim.x + threadIdx.x;
    if (e < N_EDGES) atomicAdd(&g_cnt[ei[N_EDGES + e]], 1);
}

__global__ void k_scan1() {
    __shared__ int sh[SCAN_BLK];
    int i = blockIdx.x * SCAN_BLK + threadIdx.x;
    int v = (i < N_NODES) ? g_cnt[i] : 0;
    if (i < N_NODES) g_dinv[i] = rsqrtf((float)(v + 1));
    sh[threadIdx.x] = v;
    __syncthreads();
#pragma unroll
    for (int off = 1; off < SCAN_BLK; off <<= 1) {
        int t = (threadIdx.x >= off) ? sh[threadIdx.x - off] : 0;
        __syncthreads();
        sh[threadIdx.x] += t;
        __syncthreads();
    }
    if (i < N_NODES) g_rowptr[i] = sh[threadIdx.x] - v;
    if (threadIdx.x == SCAN_BLK - 1) g_bsum[blockIdx.x] = sh[SCAN_BLK - 1];
}

__global__ void k_scan2() {
    __shared__ int sh[64];
    int v = (threadIdx.x < N_SCAN_BLOCKS) ? g_bsum[threadIdx.x] : 0;
    sh[threadIdx.x] = v;
    __syncthreads();
#pragma unroll
    for (int off = 1; off < 64; off <<= 1) {
        int t = (threadIdx.x >= off) ? sh[threadIdx.x - off] : 0;
        __syncthreads();
        sh[threadIdx.x] += t;
        __syncthreads();
    }
    g_boff[threadIdx.x] = sh[threadIdx.x] - v;
}

__global__ void k_scan3() {
    int i = blockIdx.x * blockDim.x + threadIdx.x;
    if (i < N_NODES) {
        int r = g_rowptr[i] + g_boff[i >> 10];
        g_rowptr[i] = r;
        g_cursor[i] = r;
    }
    if (i == 0) g_rowptr[N_NODES] = N_EDGES;
}

__global__ void k_fill(const int* __restrict__ ei) {
    int e = blockIdx.x * blockDim.x + threadIdx.x;
    if (e < N_EDGES) {
        int dst = ei[N_EDGES + e];
        int pos = atomicAdd(&g_cursor[dst], 1);
        g_csrc[pos] = ei[e];
    }
}

// ---------------- fused: gather(conv1) + GEMM1 + relu + GEMM2 -> ts ----------------
// grid = ceil(N/128) blocks x 512 threads; all intermediates stay in smem.
__global__ __launch_bounds__(512, 1)
void k_fused(const float* __restrict__ x, const float* __restrict__ W1,
             const float* __restrict__ b1, const float* __restrict__ W2) {
    extern __shared__ unsigned sm[];
    unsigned* As = sm;              // phase1: S1 tile tf32 [128][132]; phase2: W2s [256][36]
    unsigned* Bs = sm + AS_WORDS;   // phase1: W1 tf32 [128][264];     phase2: Hs  [128][260]

    const int tid = threadIdx.x;
    const int warpId = tid >> 5, lane = tid & 31;
    const int gid = lane >> 2, tg = lane & 3;
    const int tileM = blockIdx.x * 128;

    // ---- load W1 (128x256) as tf32 into Bs[k*264+n]
#pragma unroll
    for (int i = 0; i < 16; i++) {
        int f  = tid + i * 512;
        int k  = f >> 6;
        int n4 = (f & 63) * 4;
        float4 v = *(const float4*)&W1[k * HID1 + n4];
        uint4 o = make_uint4(f2tf32(v.x), f2tf32(v.y), f2tf32(v.z), f2tf32(v.w));
        *(uint4*)&Bs[k * 264 + n4] = o;
    }

    // ---- gather S1 tile (conv1 aggregation) into As[r*132+d]
    const float4* xv = (const float4*)x;
    for (int sub = 0; sub < 8; sub++) {
        int r = sub * 16 + warpId;
        int node = tileM + r;
        float4 acc = make_float4(0.f, 0.f, 0.f, 0.f);
        if (node < N_NODES) {
            float dw = g_dinv[node];
            float4 s = xv[node * 32 + lane];
            acc.x = dw * s.x; acc.y = dw * s.y; acc.z = dw * s.z; acc.w = dw * s.w;
            int beg = g_rowptr[node], end = g_rowptr[node + 1];
            int j = beg;
            for (; j + 3 < end; j += 4) {
                int s0 = g_csrc[j], s1 = g_csrc[j+1], s2 = g_csrc[j+2], s3 = g_csrc[j+3];
                float d0 = g_dinv[s0], d1 = g_dinv[s1], d2 = g_dinv[s2], d3 = g_dinv[s3];
                float4 v0 = xv[s0 * 32 + lane];
                float4 v1 = xv[s1 * 32 + lane];
                float4 v2 = xv[s2 * 32 + lane];
                float4 v3 = xv[s3 * 32 + lane];
                acc.x += d0*v0.x; acc.y += d0*v0.y; acc.z += d0*v0.z; acc.w += d0*v0.w;
                acc.x += d1*v1.x; acc.y += d1*v1.y; acc.z += d1*v1.z; acc.w += d1*v1.w;
                acc.x += d2*v2.x; acc.y += d2*v2.y; acc.z += d2*v2.z; acc.w += d2*v2.w;
                acc.x += d3*v3.x; acc.y += d3*v3.y; acc.z += d3*v3.z; acc.w += d3*v3.w;
            }
            for (; j < end; j++) {
                int sj = g_csrc[j];
                float dj = g_dinv[sj];
                float4 v = xv[sj * 32 + lane];
                acc.x += dj*v.x; acc.y += dj*v.y; acc.z += dj*v.z; acc.w += dj*v.w;
            }
        }
        uint4 o = make_uint4(f2tf32(acc.x), f2tf32(acc.y), f2tf32(acc.z), f2tf32(acc.w));
        *(uint4*)&As[r * 132 + lane * 4] = o;
    }
    __syncthreads();

    // ---- GEMM1 mainloop: (128x128) @ (128x256), all-resident, no inner syncs
    const int warpM = warpId & 3, warpN = warpId >> 2;   // 4M x 4N, warp tile 32x64
    float acc[2][8][4] = {};
#pragma unroll
    for (int ks = 0; ks < IN_C; ks += 8) {
        unsigned a[2][4];
#pragma unroll
        for (int mt = 0; mt < 2; mt++) {
            int rb = warpM * 32 + mt * 16;
            a[mt][0] = As[(rb + gid    ) * 132 + ks + tg    ];
            a[mt][1] = As[(rb + gid + 8) * 132 + ks + tg    ];
            a[mt][2] = As[(rb + gid    ) * 132 + ks + tg + 4];
            a[mt][3] = As[(rb + gid + 8) * 132 + ks + tg + 4];
        }
#pragma unroll
        for (int nt = 0; nt < 8; nt++) {
            int cb = warpN * 64 + nt * 8;
            unsigned b0 = Bs[(ks + tg    ) * 264 + cb + gid];
            unsigned b1v= Bs[(ks + tg + 4) * 264 + cb + gid];
            mma_tf32(acc[0][nt], a[0][0], a[0][1], a[0][2], a[0][3], b0, b1v);
            mma_tf32(acc[1][nt], a[1][0], a[1][1], a[1][2], a[1][3], b0, b1v);
        }
    }
    __syncthreads();   // everyone done reading As/Bs before repurposing

    // ---- load W2 (256x32) tf32 into As region: W2s[k*36+n]
#pragma unroll
    for (int i = 0; i < 4; i++) {
        int f = tid + i * 512;
        int k = f >> 3;
        int n4 = (f & 7) * 4;
        float4 v = *(const float4*)&W2[k * HID2 + n4];
        uint4 o = make_uint4(f2tf32(v.x), f2tf32(v.y), f2tf32(v.z), f2tf32(v.w));
        *(uint4*)&As[k * 36 + n4] = o;
    }

    // ---- epilogue1: h1 = relu(dinv*acc + b1) -> Hs (Bs region, stride 260), tf32
#pragma unroll
    for (int mt = 0; mt < 2; mt++) {
        int r0 = warpM * 32 + mt * 16 + gid;
        int r1 = r0 + 8;
        int n0 = tileM + r0, n1 = tileM + r1;
        bool v0 = n0 < N_NODES, v1 = n1 < N_NODES;
        float d0 = v0 ? g_dinv[n0] : 0.f;
        float d1 = v1 ? g_dinv[n1] : 0.f;
#pragma unroll
        for (int nt = 0; nt < 8; nt++) {
            int c = warpN * 64 + nt * 8 + tg * 2;
            float bb0 = b1[c], bb1 = b1[c + 1];
            float h00 = v0 ? fmaxf(d0 * acc[mt][nt][0] + bb0, 0.f) : 0.f;
            float h01 = v0 ? fmaxf(d0 * acc[mt][nt][1] + bb1, 0.f) : 0.f;
            float h10 = v1 ? fmaxf(d1 * acc[mt][nt][2] + bb0, 0.f) : 0.f;
            float h11 = v1 ? fmaxf(d1 * acc[mt][nt][3] + bb1, 0.f) : 0.f;
            *(uint2*)&Bs[r0 * 260 + c] = make_uint2(f2tf32(h00), f2tf32(h01));
            *(uint2*)&Bs[r1 * 260 + c] = make_uint2(f2tf32(h10), f2tf32(h11));
        }
    }
    __syncthreads();

    // ---- GEMM2: ts = dinv * (Hs(128x256) @ W2s(256x32))
    {
        int mtile = warpId >> 1;           // 8 m16 tiles
        int nh    = warpId & 1;            // 2 col halves of 16
        float a2c[2][4] = {};
#pragma unroll
        for (int ks = 0; ks < HID1; ks += 8) {
            int rb = mtile * 16;
            unsigned a0 = Bs[(rb + gid    ) * 260 + ks + tg    ];
            unsigned a1 = Bs[(rb + gid + 8) * 260 + ks + tg    ];
            unsigned a2 = Bs[(rb + gid    ) * 260 + ks + tg + 4];
            unsigned a3 = Bs[(rb + gid + 8) * 260 + ks + tg + 4];
#pragma unroll
            for (int nt = 0; nt < 2; nt++) {
                int cb = nh * 16 + nt * 8;
                unsigned b0 = As[(ks + tg    ) * 36 + cb + gid];
                unsigned b1v= As[(ks + tg + 4) * 36 + cb + gid];
                mma_tf32(a2c[nt], a0, a1, a2, a3, b0, b1v);
            }
        }
        int r0 = tileM + mtile * 16 + gid;
        int r1 = r0 + 8;
        float d0 = (r0 < N_NODES) ? g_dinv[r0] : 0.f;
        float d1 = (r1 < N_NODES) ? g_dinv[r1] : 0.f;
#pragma unroll
        for (int nt = 0; nt < 2; nt++) {
            int c = nh * 16 + nt * 8 + tg * 2;
            if (r0 < N_NODES)
                *(float2*)&g_ts[r0 * HID2 + c] = make_float2(d0 * a2c[nt][0], d0 * a2c[nt][1]);
            if (r1 < N_NODES)
                *(float2*)&g_ts[r1 * HID2 + c] = make_float2(d1 * a2c[nt][2], d1 * a2c[nt][3]);
        }
    }
}

// ---------------- conv2 gather + z ----------------
__global__ void k_agg2(const float* __restrict__ b2) {
    int w = (blockIdx.x * blockDim.x + threadIdx.x) >> 5;
    if (w >= N_NODES) return;
    int lane = threadIdx.x & 31;
    int beg = g_rowptr[w], end = g_rowptr[w + 1];
    float acc = g_ts[w * 32 + lane];
    int j = beg;
    for (; j + 3 < end; j += 4) {
        int s0 = g_csrc[j], s1 = g_csrc[j + 1], s2 = g_csrc[j + 2], s3 = g_csrc[j + 3];
        acc += g_ts[s0 * 32 + lane];
        acc += g_ts[s1 * 32 + lane];
        acc += g_ts[s2 * 32 + lane];
        acc += g_ts[s3 * 32 + lane];
    }
    for (; j < end; j++) acc += g_ts[g_csrc[j] * 32 + lane];
    g_z[w * 32 + lane] = g_dinv[w] * acc + b2[lane];
}

// ---------------- decode: 8 lanes per edge, float4 loads ----------------
__global__ void k_decode(const int* __restrict__ eli, float* __restrict__ out) {
    int t = blockIdx.x * blockDim.x + threadIdx.x;
    int k = t >> 3;
    if (k >= N_LABEL) return;
    int lane = t & 7;
    int a = eli[k];
    int b = eli[N_LABEL + k];
    float4 za = ((const float4*)g_z)[a * 8 + lane];
    float4 zb = ((const float4*)g_z)[b * 8 + lane];
    float p = za.x * zb.x + za.y * zb.y + za.z * zb.z + za.w * zb.w;
    p += __shfl_xor_sync(0xffffffffu, p, 4);
    p += __shfl_xor_sync(0xffffffffu, p, 2);
    p += __shfl_xor_sync(0xffffffffu, p, 1);
    if (lane == 0) out[k] = p;
}

// ---------------- launch ----------------
extern "C" void kernel_launch(void* const* d_in, const int* in_sizes, int n_in,
                              void* d_out, int out_size) {
    const float* x   = (const float*)d_in[0];
    const int*   ei  = (const int*)d_in[1];     // int32 (JAX x64 disabled)
    const int*   eli = (const int*)d_in[2];
    const float* W1  = (const float*)d_in[3];
    const float* b1  = (const float*)d_in[4];
    const float* W2  = (const float*)d_in[5];
    const float* b2  = (const float*)d_in[6];
    float* out = (float*)d_out;
    (void)in_sizes; (void)n_in; (void)out_size;

    cudaFuncSetAttribute(k_fused, cudaFuncAttributeMaxDynamicSharedMemorySize,
                         SMEM_WORDS * 4);

    k_zero_cnt<<<(N_NODES + 255) / 256, 256>>>();
    k_hist    <<<(N_EDGES + 255) / 256, 256>>>(ei);
    k_scan1   <<<N_SCAN_BLOCKS, SCAN_BLK>>>();
    k_scan2   <<<1, 64>>>();
    k_scan3   <<<(N_NODES + 255) / 256, 256>>>();
    k_fill    <<<(N_EDGES + 255) / 256, 256>>>(ei);

    k_fused   <<<(N_NODES + 127) / 128, 512, SMEM_WORDS * 4>>>(x, W1, b1, W2);

    k_agg2    <<<(N_NODES * 32 + 255) / 256, 256>>>(b2);
    k_decode  <<<(N_LABEL * 8 + 255) / 256, 256>>>(eli, out);
}